// round 16
// speedup vs baseline: 8.7068x; 1.0372x over previous
#include <cuda_runtime.h>
#include <cuda_bf16.h>
#include <math.h>
#include <stdint.h>

#define NN   8192
#define DIN  561
#define DH   256
#define NE   262144
#define NCLS 6
#define DINP 640
#define KHP  576

#define OFF_COEF 6
#define OFF_CONS 67108870
#define OFF_SREG 67108871
#define OFF_CQ   67108872
#define OFF_H1   67108873
#define OFF_H2   69206025

#define ACC_FEAT   0
#define ACC_SE     1
#define ACC_SREG   2
#define ACC_CQ     3
#define ACC_DENSE  4
#define ACC_STRUCT 5
#define ACC_CONS   6
#define ACC_CQT    7

// ---------------- scratch ----------------------------------------------------
__device__ double g_acc[8];
__device__ double g_cs[512];
__device__ int    g_wflag;
__device__ float  g_wval;
__device__ float  g_H1[NN * DH];
__device__ float  g_H2[NN * DH];
__device__ float  g_HC[NN * 512];   // fallback only
__device__ __align__(16) __nv_bfloat16 g_W0bf[DINP * DH];
__device__ __align__(16) __nv_bfloat16 g_W0Thi[DH * KHP];
__device__ __align__(16) __nv_bfloat16 g_W0Tlo[DH * KHP];
__device__ __align__(16) __nv_bfloat16 g_Hbf1[NN * DH];
__device__ __align__(16) __nv_bfloat16 g_Hbf2[NN * DH];
__device__ float  g_HCenc1[NN * DH];
__device__ float  g_HCenc2[NN * DH];
__device__ float  g_f1a[NN], g_f2a[NN], g_f1b[NN], g_f2b[NN];
__device__ float  g_att1[NE], g_att2[NE];
__device__ int    g_cnt1[NN], g_cnt2[NN];
__device__ int    g_rp1[NN + 1], g_rp2[NN + 1];
__device__ int    g_cur1[NN], g_cur2[NN];
__device__ int    g_ecsr1[NE], g_ecsr2[NE];
__device__ float  g_M1[NCLS * DH], g_M2[NCLS * DH], g_b1[NCLS], g_b2[NCLS];
__device__ __align__(16) __nv_bfloat16 g_HcatT[(size_t)512 * NN];   // fallback only

// ---------------- ptx helpers -------------------------------------------------
__device__ __forceinline__ uint32_t smem_u32(const void* p) {
    uint32_t a;
    asm("{ .reg .u64 t; cvta.to.shared.u64 t, %1; cvt.u32.u64 %0, t; }" : "=r"(a) : "l"(p));
    return a;
}

__device__ __forceinline__ void ldm_x4(uint32_t& r0, uint32_t& r1, uint32_t& r2, uint32_t& r3,
                                       uint32_t addr) {
    asm volatile("ldmatrix.sync.aligned.m8n8.x4.shared.b16 {%0,%1,%2,%3}, [%4];"
                 : "=r"(r0), "=r"(r1), "=r"(r2), "=r"(r3) : "r"(addr));
}

__device__ __forceinline__ void mma_bf16(float* c, const uint32_t* a, uint32_t b0, uint32_t b1) {
    asm volatile(
        "mma.sync.aligned.m16n8k16.row.col.f32.bf16.bf16.f32 "
        "{%0,%1,%2,%3}, {%4,%5,%6,%7}, {%8,%9}, {%0,%1,%2,%3};"
        : "+f"(c[0]), "+f"(c[1]), "+f"(c[2]), "+f"(c[3])
        : "r"(a[0]), "r"(a[1]), "r"(a[2]), "r"(a[3]), "r"(b0), "r"(b1));
}

__device__ __forceinline__ uint4 cvt_f32x8_bf16x8(float4 f0, float4 f1) {
    __nv_bfloat162 b0 = __floats2bfloat162_rn(f0.x, f0.y);
    __nv_bfloat162 b1 = __floats2bfloat162_rn(f0.z, f0.w);
    __nv_bfloat162 b2 = __floats2bfloat162_rn(f1.x, f1.y);
    __nv_bfloat162 b3 = __floats2bfloat162_rn(f1.z, f1.w);
    uint4 u;
    u.x = *(uint32_t*)&b0; u.y = *(uint32_t*)&b1;
    u.z = *(uint32_t*)&b2; u.w = *(uint32_t*)&b3;
    return u;
}

// ---------------- helpers ----------------------------------------------------
__device__ __forceinline__ double block_reduce_d(double v) {
    __shared__ double red[32];
    int tid  = threadIdx.y * blockDim.x + threadIdx.x;
    int nth  = blockDim.x * blockDim.y;
    int lane = tid & 31, w = tid >> 5;
#pragma unroll
    for (int o = 16; o; o >>= 1) v += __shfl_down_sync(0xffffffffu, v, o);
    __syncthreads();
    if (lane == 0) red[w] = v;
    __syncthreads();
    double r = 0.0;
    if (w == 0) {
        int nw = (nth + 31) >> 5;
        r = (lane < nw) ? red[lane] : 0.0;
#pragma unroll
        for (int o = 16; o; o >>= 1) r += __shfl_down_sync(0xffffffffu, r, o);
    }
    return r;
}

// ---------------- init --------------------------------------------------------
__global__ void zero_kernel() {
    int t = blockIdx.x * blockDim.x + threadIdx.x;
    if (t < 8) g_acc[t] = 0.0;
    if (t < 512) g_cs[t] = 0.0;
    if (t == 0) g_wflag = 1;
    if (t < NN) {
        g_cnt1[t] = 0; g_cnt2[t] = 0;
        g_f1a[t] = 0.f; g_f2a[t] = 0.f; g_f1b[t] = 0.f; g_f2b[t] = 0.f;
    }
}

__global__ void w0bf_kernel(const float* __restrict__ W0) {
    int t = blockIdx.x * blockDim.x + threadIdx.x;
    if (t < DINP * DH) {
        int din = t / DH, dh = t % DH;
        float v = (din < DIN) ? W0[din * DH + dh] : 0.f;
        g_W0bf[t] = __float2bfloat16(v);
    }
}

__global__ void w0split_kernel(const float* __restrict__ W0) {
    int t = blockIdx.x * blockDim.x + threadIdx.x;
    if (t < DH * KHP) {
        int n = t / KHP, k = t % KHP;
        float v = (k < DIN) ? W0[k * DH + n] : 0.f;
        __nv_bfloat16 hi = __float2bfloat16(v);
        float lo = v - __bfloat162float(hi);
        g_W0Thi[t] = hi;
        g_W0Tlo[t] = __float2bfloat16(lo);
    }
}

// ---- merged coef pass: writes general coef, exact S_Regular, |Theta| sum,
//      constancy flag (one pass over weight + Theta) -------------------------
__global__ void coefall_kernel(const float* __restrict__ w, const float* __restrict__ Theta,
                               float* __restrict__ coef) {
    float w0 = __ldg(w);
    long t0 = (long)blockIdx.x * blockDim.x + threadIdx.x;
    const long n4 = (long)NN * NN / 4;
    const long stride = (long)gridDim.x * blockDim.x;
    bool ok = true;
    float sreg = 0.f;
    float cqt = 0.f;
    for (long t = t0; t < n4; t += stride) {
        long i = t << 2;
        int a = (int)(i >> 13);
        int b = (int)(i & 8191);
        float4 wv = __ldcs((const float4*)w + t);
        float4 th = __ldcs((const float4*)Theta + t);
        ok &= (wv.x == w0) & (wv.y == w0) & (wv.z == w0) & (wv.w == w0);
        float s = fabsf(th.x) + fabsf(th.y) + fabsf(th.z) + fabsf(th.w);
        int d = a - b;
        if (d >= 0 && d < 4) {
            if (d == 0)      { wv.x = 0.f; s -= fabsf(th.x); }
            else if (d == 1) { wv.y = 0.f; s -= fabsf(th.y); }
            else if (d == 2) { wv.z = 0.f; s -= fabsf(th.z); }
            else             { wv.w = 0.f; s -= fabsf(th.w); }
        }
        sreg += fabsf(wv.x) + fabsf(wv.y) + fabsf(wv.z) + fabsf(wv.w);
        cqt  += s;
        float2* c2 = (float2*)(coef + i);
        __stcs(&c2[0], make_float2(wv.x, wv.y));
        __stcs(&c2[1], make_float2(wv.z, wv.w));
    }
    if (!ok) g_wflag = 0;
    if (t0 == 0) g_wval = w0;
    double r1 = block_reduce_d((double)sreg);
    double r2 = block_reduce_d((double)cqt);
    if (threadIdx.x == 0) {
        atomicAdd(&g_acc[ACC_SREG], r1);
        atomicAdd(&g_acc[ACC_CQT],  r2);
    }
}

// Cq fallback (non-constant weight only): sum |coef[a,b] * Theta[b,a]|
__global__ void cqfb_kernel(const float* __restrict__ w, const float* __restrict__ Theta) {
    if (g_wflag) return;
    long t0 = (long)blockIdx.x * blockDim.x + threadIdx.x;
    const long n = (long)NN * NN;
    const long stride = (long)gridDim.x * blockDim.x;
    double cq = 0.0;
    for (long i = t0; i < n; i += stride) {
        int a = (int)(i >> 13);
        int b = (int)(i & 8191);
        if (a != b)
            cq += fabs((double)w[i] * (double)Theta[(long)b * NN + a]);
    }
    double tot = block_reduce_d(cq);
    if (threadIdx.x == 0) atomicAdd(&g_acc[ACC_CQ], tot);
}

// ---------------- split-bf16 HMMA: H = X @ W0, fused f1/f2 ---------------------
#define KCH   64
#define TSTR  144
#define TILEB (128 * TSTR)

__global__ void __launch_bounds__(256, 1)
gemm_h_kernel(const float* __restrict__ X, float* __restrict__ H,
              const float* __restrict__ v0, const float* __restrict__ v1,
              float* __restrict__ f1, float* __restrict__ f2) {
    extern __shared__ __align__(16) char dsm[];
    const int tid  = threadIdx.x;
    const int wid  = tid >> 5;
    const int lane = tid & 31;
    const long m0 = (long)blockIdx.y * 128;
    const int  n0 = blockIdx.x * 128;

    char* sAhi = dsm;
    char* sAlo = dsm + TILEB;
    char* sBhi = dsm + 2 * TILEB;
    char* sBlo = dsm + 3 * TILEB;

    float acc[2][8][4] = {};

    const int mw = (wid >> 1) * 32;
    const int nw = (wid & 1) * 64;
    const int grp = lane >> 3, lr = lane & 7;

    for (int kt = 0; kt < KHP / KCH; kt++) {
        const int k0 = kt * KCH;
        __syncthreads();
#pragma unroll
        for (int i = 0; i < 4; i++) {
            int idx = tid + i * 256;
            int r = idx >> 3, c8 = (idx & 7) * 8;
            const float* xp = X + (m0 + r) * (long)DIN + k0 + c8;
            float v[8];
#pragma unroll
            for (int j = 0; j < 8; j++) {
                int kk = k0 + c8 + j;
                v[j] = (kk < DIN) ? xp[j] : 0.f;
            }
            __nv_bfloat16 hi[8]; float lo[8];
#pragma unroll
            for (int j = 0; j < 8; j++) {
                hi[j] = __float2bfloat16(v[j]);
                lo[j] = v[j] - __bfloat162float(hi[j]);
            }
            uint4 uh, ul;
            {
                __nv_bfloat162 h0 = {hi[0], hi[1]}, h1 = {hi[2], hi[3]};
                __nv_bfloat162 h2 = {hi[4], hi[5]}, h3 = {hi[6], hi[7]};
                uh.x = *(uint32_t*)&h0; uh.y = *(uint32_t*)&h1;
                uh.z = *(uint32_t*)&h2; uh.w = *(uint32_t*)&h3;
                float4 l0 = make_float4(lo[0], lo[1], lo[2], lo[3]);
                float4 l1 = make_float4(lo[4], lo[5], lo[6], lo[7]);
                ul = cvt_f32x8_bf16x8(l0, l1);
            }
            *(uint4*)(sAhi + r * TSTR + c8 * 2) = uh;
            *(uint4*)(sAlo + r * TSTR + c8 * 2) = ul;
            *(uint4*)(sBhi + r * TSTR + c8 * 2) =
                *(const uint4*)(g_W0Thi + (n0 + r) * KHP + k0 + c8);
            *(uint4*)(sBlo + r * TSTR + c8 * 2) =
                *(const uint4*)(g_W0Tlo + (n0 + r) * KHP + k0 + c8);
        }
        __syncthreads();

        const uint32_t sAh = smem_u32(sAhi);
        const uint32_t sAl = smem_u32(sAlo);
        const uint32_t sBh = smem_u32(sBhi);
        const uint32_t sBl = smem_u32(sBlo);
#pragma unroll
        for (int ks = 0; ks < KCH / 16; ks++) {
            const int k16 = ks * 16;
            uint32_t ah[2][4], al[2][4];
#pragma unroll
            for (int mi = 0; mi < 2; mi++) {
                int row = mw + mi * 16 + (grp & 1) * 8 + lr;
                int coloff = (k16 + (grp >> 1) * 8) * 2;
                ldm_x4(ah[mi][0], ah[mi][1], ah[mi][2], ah[mi][3], sAh + row * TSTR + coloff);
                ldm_x4(al[mi][0], al[mi][1], al[mi][2], al[mi][3], sAl + row * TSTR + coloff);
            }
            uint32_t bh[4][4], bl[4][4];
#pragma unroll
            for (int g = 0; g < 4; g++) {
                int n = nw + g * 16 + (grp >> 1) * 8 + lr;
                int coloff = (k16 + (grp & 1) * 8) * 2;
                ldm_x4(bh[g][0], bh[g][1], bh[g][2], bh[g][3], sBh + n * TSTR + coloff);
                ldm_x4(bl[g][0], bl[g][1], bl[g][2], bl[g][3], sBl + n * TSTR + coloff);
            }
#pragma unroll
            for (int mi = 0; mi < 2; mi++)
#pragma unroll
                for (int g = 0; g < 4; g++) {
                    mma_bf16(acc[mi][g * 2],     ah[mi], bh[g][0], bh[g][1]);
                    mma_bf16(acc[mi][g * 2 + 1], ah[mi], bh[g][2], bh[g][3]);
                    mma_bf16(acc[mi][g * 2],     ah[mi], bl[g][0], bl[g][1]);
                    mma_bf16(acc[mi][g * 2 + 1], ah[mi], bl[g][2], bl[g][3]);
                    mma_bf16(acc[mi][g * 2],     al[mi], bh[g][0], bh[g][1]);
                    mma_bf16(acc[mi][g * 2 + 1], al[mi], bh[g][2], bh[g][3]);
                }
        }
    }

#pragma unroll
    for (int mi = 0; mi < 2; mi++) {
        long r0 = m0 + mw + mi * 16 + (lane >> 2);
        long r1 = r0 + 8;
        float s0a = 0.f, s0b = 0.f, s1a = 0.f, s1b = 0.f;
#pragma unroll
        for (int nt = 0; nt < 8; nt++) {
            int cc = n0 + nw + nt * 8 + (lane & 3) * 2;
            H[r0 * DH + cc]     = acc[mi][nt][0];
            H[r0 * DH + cc + 1] = acc[mi][nt][1];
            H[r1 * DH + cc]     = acc[mi][nt][2];
            H[r1 * DH + cc + 1] = acc[mi][nt][3];
            float va = v0[cc], vb = v0[cc + 1];
            float wa = v1[cc], wb = v1[cc + 1];
            s0a += acc[mi][nt][0] * va + acc[mi][nt][1] * vb;
            s0b += acc[mi][nt][0] * wa + acc[mi][nt][1] * wb;
            s1a += acc[mi][nt][2] * va + acc[mi][nt][3] * vb;
            s1b += acc[mi][nt][2] * wa + acc[mi][nt][3] * wb;
        }
        s0a += __shfl_down_sync(0xffffffffu, s0a, 2);
        s0a += __shfl_down_sync(0xffffffffu, s0a, 1);
        s0b += __shfl_down_sync(0xffffffffu, s0b, 2);
        s0b += __shfl_down_sync(0xffffffffu, s0b, 1);
        s1a += __shfl_down_sync(0xffffffffu, s1a, 2);
        s1a += __shfl_down_sync(0xffffffffu, s1a, 1);
        s1b += __shfl_down_sync(0xffffffffu, s1b, 2);
        s1b += __shfl_down_sync(0xffffffffu, s1b, 1);
        if ((lane & 3) == 0) {
            atomicAdd(&f1[r0], s0a);
            atomicAdd(&f2[r0], s0b);
            atomicAdd(&f1[r1], s1a);
            atomicAdd(&f2[r1], s1b);
        }
    }
}

// ---------------- bf16 HMMA GEMM (FALLBACK: coef @ Hcat) -----------------------
#define NKCH  (NN / KCH)

__global__ void __launch_bounds__(256, 1)
gemm_mma_kernel(const float* __restrict__ A,
                const __nv_bfloat16* __restrict__ Bt,
                float* __restrict__ C) {
    if (g_wflag) return;
    extern __shared__ __align__(16) char dsm[];
    const int tid  = threadIdx.x;
    const int wid  = tid >> 5;
    const int lane = tid & 31;
    const long m0 = (long)blockIdx.y * 128;
    const long n0 = (long)blockIdx.x * 128;

    const int offA[2] = {0, 2 * TILEB};
    const int offB[2] = {TILEB, 3 * TILEB};

    float acc[2][8][4] = {};

    {
        char* sA = dsm + offA[0];
        char* sB = dsm + offB[0];
#pragma unroll
        for (int i = 0; i < 4; i++) {
            int idx = tid + i * 256;
            int r = idx >> 3, c8 = (idx & 7) * 8;
            const float* ap = A + (m0 + r) * (long)NN + c8;
            float4 f0, f1;
            f0.x = ap[0]; f0.y = ap[1]; f0.z = ap[2]; f0.w = ap[3];
            f1.x = ap[4]; f1.y = ap[5]; f1.z = ap[6]; f1.w = ap[7];
            *(uint4*)(sA + r * TSTR + c8 * 2) = cvt_f32x8_bf16x8(f0, f1);
            *(uint4*)(sB + r * TSTR + c8 * 2) = *(const uint4*)(Bt + (n0 + r) * (long)NN + c8);
        }
    }
    __syncthreads();

    const int mw = (wid >> 1) * 32;
    const int nw = (wid & 1) * 64;
    const int grp = lane >> 3, lr = lane & 7;

    for (int kt = 0; kt < NKCH; kt++) {
        const int buf = kt & 1;
        float4 rfa[4][2]; uint4 rb[4];
        if (kt + 1 < NKCH) {
            long k0 = (long)(kt + 1) * KCH;
#pragma unroll
            for (int i = 0; i < 4; i++) {
                int idx = tid + i * 256;
                int r = idx >> 3, c8 = (idx & 7) * 8;
                const float* ap = A + (m0 + r) * (long)NN + k0 + c8;
                rfa[i][0].x = ap[0]; rfa[i][0].y = ap[1];
                rfa[i][0].z = ap[2]; rfa[i][0].w = ap[3];
                rfa[i][1].x = ap[4]; rfa[i][1].y = ap[5];
                rfa[i][1].z = ap[6]; rfa[i][1].w = ap[7];
                rb[i] = *(const uint4*)(Bt + (n0 + r) * (long)NN + k0 + c8);
            }
        }

        const uint32_t sAb = smem_u32(dsm + offA[buf]);
        const uint32_t sBb = smem_u32(dsm + offB[buf]);
#pragma unroll
        for (int ks = 0; ks < KCH / 16; ks++) {
            const int k16 = ks * 16;
            uint32_t a[2][4];
#pragma unroll
            for (int mi = 0; mi < 2; mi++) {
                int row = mw + mi * 16 + (grp & 1) * 8 + lr;
                int col = k16 + (grp >> 1) * 8;
                ldm_x4(a[mi][0], a[mi][1], a[mi][2], a[mi][3], sAb + row * TSTR + col * 2);
            }
            uint32_t b[4][4];
#pragma unroll
            for (int g = 0; g < 4; g++) {
                int n = nw + g * 16 + (grp >> 1) * 8 + lr;
                int col = k16 + (grp & 1) * 8;
                ldm_x4(b[g][0], b[g][1], b[g][2], b[g][3], sBb + n * TSTR + col * 2);
            }
#pragma unroll
            for (int mi = 0; mi < 2; mi++)
#pragma unroll
                for (int g = 0; g < 4; g++) {
                    mma_bf16(acc[mi][g * 2],     a[mi], b[g][0], b[g][1]);
                    mma_bf16(acc[mi][g * 2 + 1], a[mi], b[g][2], b[g][3]);
                }
        }
        __syncthreads();
        if (kt + 1 < NKCH) {
            char* sA = dsm + offA[buf ^ 1];
            char* sB = dsm + offB[buf ^ 1];
#pragma unroll
            for (int i = 0; i < 4; i++) {
                int idx = tid + i * 256;
                int r = idx >> 3, c8 = (idx & 7) * 8;
                *(uint4*)(sA + r * TSTR + c8 * 2) = cvt_f32x8_bf16x8(rfa[i][0], rfa[i][1]);
                *(uint4*)(sB + r * TSTR + c8 * 2) = rb[i];
            }
            __syncthreads();
        }
    }

#pragma unroll
    for (int mi = 0; mi < 2; mi++) {
        long r0 = m0 + mw + mi * 16 + (lane >> 2);
        long r1 = r0 + 8;
#pragma unroll
        for (int nt = 0; nt < 8; nt++) {
            long cc = n0 + nw + nt * 8 + (lane & 3) * 2;
            float* c0 = C + r0 * 512 + cc;
            float* c1 = C + r1 * 512 + cc;
            c0[0] = acc[mi][nt][0]; c0[1] = acc[mi][nt][1];
            c1[0] = acc[mi][nt][2]; c1[1] = acc[mi][nt][3];
        }
    }
}

// ------- bf16 HMMA + fused features loss ---------------------------------------
#define NKR 4

__global__ void __launch_bounds__(256, 1)
gemm_recx_kernel(const float* __restrict__ A, const float* __restrict__ X) {
    extern __shared__ __align__(16) char dsm[];
    const int tid  = threadIdx.x;
    const int wid  = tid >> 5;
    const int lane = tid & 31;
    const long m0 = (long)blockIdx.y * 128;
    const int  n0 = blockIdx.x * 128;

    const int offA[2] = {0, 2 * TILEB};
    const int offB[2] = {TILEB, 3 * TILEB};

    float acc[2][8][4] = {};

    {
        char* sA = dsm + offA[0];
        char* sB = dsm + offB[0];
#pragma unroll
        for (int i = 0; i < 4; i++) {
            int idx = tid + i * 256;
            int r = idx >> 3, c8 = (idx & 7) * 8;
            const float* ap = A + (m0 + r) * DH + c8;
            float4 f0 = *(const float4*)ap;
            float4 f1 = *(const float4*)(ap + 4);
            *(uint4*)(sA + r * TSTR + c8 * 2) = cvt_f32x8_bf16x8(f0, f1);
            *(uint4*)(sB + r * TSTR + c8 * 2) = *(const uint4*)(g_W0bf + (n0 + r) * DH + c8);
        }
    }
    __syncthreads();

    const int mw = (wid >> 1) * 32;
    const int nw = (wid & 1) * 64;
    const int grp = lane >> 3, lr = lane & 7;

    for (int kt = 0; kt < NKR; kt++) {
        const int buf = kt & 1;
        float4 rfa[4][2]; uint4 rb[4];
        if (kt + 1 < NKR) {
            int k0 = (kt + 1) * KCH;
#pragma unroll
            for (int i = 0; i < 4; i++) {
                int idx = tid + i * 256;
                int r = idx >> 3, c8 = (idx & 7) * 8;
                const float* ap = A + (m0 + r) * DH + k0 + c8;
                rfa[i][0] = *(const float4*)ap;
                rfa[i][1] = *(const float4*)(ap + 4);
                rb[i] = *(const uint4*)(g_W0bf + (n0 + r) * DH + k0 + c8);
            }
        }

        const uint32_t sAb = smem_u32(dsm + offA[buf]);
        const uint32_t sBb = smem_u32(dsm + offB[buf]);
#pragma unroll
        for (int ks = 0; ks < KCH / 16; ks++) {
            const int k16 = ks * 16;
            uint32_t a[2][4];
#pragma unroll
            for (int mi = 0; mi < 2; mi++) {
                int row = mw + mi * 16 + (grp & 1) * 8 + lr;
                int col = k16 + (grp >> 1) * 8;
                ldm_x4(a[mi][0], a[mi][1], a[mi][2], a[mi][3], sAb + row * TSTR + col * 2);
            }
            uint32_t b[4][4];
#pragma unroll
            for (int g = 0; g < 4; g++) {
                int n = nw + g * 16 + (grp >> 1) * 8 + lr;
                int col = k16 + (grp & 1) * 8;
                ldm_x4(b[g][0], b[g][1], b[g][2], b[g][3], sBb + n * TSTR + col * 2);
            }
#pragma unroll
            for (int mi = 0; mi < 2; mi++)
#pragma unroll
                for (int g = 0; g < 4; g++) {
                    mma_bf16(acc[mi][g * 2],     a[mi], b[g][0], b[g][1]);
                    mma_bf16(acc[mi][g * 2 + 1], a[mi], b[g][2], b[g][3]);
                }
        }
        __syncthreads();
        if (kt + 1 < NKR) {
            char* sA = dsm + offA[buf ^ 1];
            char* sB = dsm + offB[buf ^ 1];
#pragma unroll
            for (int i = 0; i < 4; i++) {
                int idx = tid + i * 256;
                int r = idx >> 3, c8 = (idx & 7) * 8;
                *(uint4*)(sA + r * TSTR + c8 * 2) = cvt_f32x8_bf16x8(rfa[i][0], rfa[i][1]);
                *(uint4*)(sB + r * TSTR + c8 * 2) = rb[i];
            }
            __syncthreads();
        }
    }

    double part = 0.0;
#pragma unroll
    for (int mi = 0; mi < 2; mi++) {
        long r0 = m0 + mw + mi * 16 + (lane >> 2);
        long r1 = r0 + 8;
#pragma unroll
        for (int nt = 0; nt < 8; nt++) {
            int cc = n0 + nw + nt * 8 + (lane & 3) * 2;
            if (cc < DIN) {
                float d0 = X[r0 * DIN + cc] - acc[mi][nt][0];
                float d2 = X[r1 * DIN + cc] - acc[mi][nt][2];
                part += (double)d0 * d0 + (double)d2 * d2;
            }
            if (cc + 1 < DIN) {
                float d1 = X[r0 * DIN + cc + 1] - acc[mi][nt][1];
                float d3 = X[r1 * DIN + cc + 1] - acc[mi][nt][3];
                part += (double)d1 * d1 + (double)d3 * d3;
            }
        }
    }
    double tot = block_reduce_d(part);
    if (tid == 0) atomicAdd(&g_acc[ACC_FEAT], tot);
}

// ---------------- per-view colsum -----------------------------------------------
__global__ void colsum_kernel(const float* __restrict__ H, double* __restrict__ csout) {
    int d = threadIdx.x;
    long r0 = (long)blockIdx.x * 128;
    float s = 0.f;
    for (int i = 0; i < 128; i++) s += H[(r0 + i) * DH + d];
    atomicAdd(&csout[d], (double)s);
}

// ---------------- transpose Henc -> HcatT (FALLBACK only) ----------------------
__global__ void tr_kernel(const float* __restrict__ H1, const float* __restrict__ H2) {
    if (g_wflag) return;
    __shared__ float t[32][33];
    int k0 = blockIdx.x * 32;
    int n0 = blockIdx.y * 32;
    const float* src = (n0 < 256) ? H1 : H2;
    int nn0 = n0 & 255;
    int tx = threadIdx.x, ty = threadIdx.y;
#pragma unroll
    for (int i = 0; i < 4; i++)
        t[ty + i * 8][tx] = src[(long)(k0 + ty + i * 8) * DH + nn0 + tx];
    __syncthreads();
#pragma unroll
    for (int i = 0; i < 4; i++)
        g_HcatT[(long)(n0 + ty + i * 8) * NN + k0 + tx] = __float2bfloat16(t[tx][ty + i * 8]);
}

// ---------------- attention pipeline -----------------------------------------
__global__ void cnt_kernel(const int* __restrict__ row, int* __restrict__ cnt) {
    int e = blockIdx.x * blockDim.x + threadIdx.x;
    if (e < NE) atomicAdd(&cnt[row[e]], 1);
}

__global__ void scan_kernel(const int* __restrict__ cnt, int* __restrict__ rp,
                            int* __restrict__ cur) {
    __shared__ int sm[1024];
    int tid = threadIdx.x;
    int base = tid * 8;
    int loc[8]; int s = 0;
#pragma unroll
    for (int j = 0; j < 8; j++) { loc[j] = s; s += cnt[base + j]; }
    sm[tid] = s;
    __syncthreads();
    for (int o = 1; o < 1024; o <<= 1) {
        int v = (tid >= o) ? sm[tid - o] : 0;
        __syncthreads();
        sm[tid] += v;
        __syncthreads();
    }
    int off = tid ? sm[tid - 1] : 0;
#pragma unroll
    for (int j = 0; j < 8; j++) { int x = off + loc[j]; rp[base + j] = x; cur[base + j] = x; }
    if (tid == 1023) rp[NN] = sm[1023];
}

__global__ void fill_kernel(const int* __restrict__ row, int* __restrict__ cur,
                            int* __restrict__ ecsr) {
    int e = blockIdx.x * blockDim.x + threadIdx.x;
    if (e < NE) { int pos = atomicAdd(&cur[row[e]], 1); ecsr[pos] = e; }
}

__global__ void att_kernel(const int* __restrict__ col, const float* __restrict__ f1,
                           const float* __restrict__ f2, const int* __restrict__ rp,
                           const int* __restrict__ ecsr, float* __restrict__ att) {
    int warp = (blockIdx.x * blockDim.x + threadIdx.x) >> 5;
    int lane = threadIdx.x & 31;
    if (warp >= NN) return;
    int s = rp[warp], t = rp[warp + 1];
    float fr = f1[warp];
    int lim = min(t, s + 128);
    float uc[4];
    float m = -1e30f;
#pragma unroll
    for (int j = 0; j < 4; j++) {
        int i = s + lane + j * 32;
        if (i < lim) {
            int e = ecsr[i];
            float u = 1.f / (1.f + expf(-(fr + f2[col[e]])));
            uc[j] = u;
            m = fmaxf(m, u);
        }
    }
    for (int i = s + 128 + lane; i < t; i += 32) {
        int e = ecsr[i];
        float u = 1.f / (1.f + expf(-(fr + f2[col[e]])));
        m = fmaxf(m, u);
    }
#pragma unroll
    for (int o = 16; o; o >>= 1) m = fmaxf(m, __shfl_xor_sync(0xffffffffu, m, o));
    float ss = 0.f;
#pragma unroll
    for (int j = 0; j < 4; j++) {
        int i = s + lane + j * 32;
        if (i < lim) ss += expf(uc[j] - m);
    }
    for (int i = s + 128 + lane; i < t; i += 32) {
        int e = ecsr[i];
        float u = 1.f / (1.f + expf(-(fr + f2[col[e]])));
        ss += expf(u - m);
    }
#pragma unroll
    for (int o = 16; o; o >>= 1) ss += __shfl_xor_sync(0xffffffffu, ss, o);
    float inv = 1.f / (ss + 1e-12f);
#pragma unroll
    for (int j = 0; j < 4; j++) {
        int i = s + lane + j * 32;
        if (i < lim) att[ecsr[i]] = expf(uc[j] - m) * inv;
    }
    for (int i = s + 128 + lane; i < t; i += 32) {
        int e = ecsr[i];
        float u = 1.f / (1.f + expf(-(fr + f2[col[e]])));
        att[e] = expf(u - m) * inv;
    }
}

__global__ void henc_kernel(const int* __restrict__ col, const float* __restrict__ att,
                            const int* __restrict__ rp, const int* __restrict__ ecsr,
                            const float* __restrict__ Hsrc, float* __restrict__ Hout,
                            __nv_bfloat16* __restrict__ Hbf) {
    __shared__ int   s_col[64];
    __shared__ float s_att[64];
    int r = blockIdx.x, tid = threadIdx.x;
    int s = rp[r], t = rp[r + 1];
    float acc = 0.f;
    for (int base = s; base < t; base += 64) {
        int c = min(64, t - base);
        __syncthreads();
        if (tid < c) { int e = ecsr[base + tid]; s_col[tid] = col[e]; s_att[tid] = att[e]; }
        __syncthreads();
        for (int i = 0; i < c; i++) acc += s_att[i] * Hsrc[(long)s_col[i] * DH + tid];
    }
    Hout[(long)r * DH + tid] = acc;
    Hbf[(long)r * DH + tid] = __float2bfloat16(acc);
}

// merged HCenc gather: fast path (Hbf + cs) or fallback (HC)
__global__ void henchc_any_kernel(const int* __restrict__ col, const float* __restrict__ att,
                                  const int* __restrict__ rp, const int* __restrict__ ecsr,
                                  const __nv_bfloat16* __restrict__ Hbf,
                                  const float* __restrict__ HCoff,
                                  const double* __restrict__ cs,
                                  float* __restrict__ Hout) {
    __shared__ int   s_col[64];
    __shared__ float s_att[64];
    int r = blockIdx.x, tid = threadIdx.x;
    int s = rp[r], t = rp[r + 1];
    int fast = g_wflag;
    float acc = 0.f;
    for (int base = s; base < t; base += 64) {
        int c = min(64, t - base);
        __syncthreads();
        if (tid < c) { int e = ecsr[base + tid]; s_col[tid] = col[e]; s_att[tid] = att[e]; }
        __syncthreads();
        if (fast) {
            for (int i = 0; i < c; i++)
                acc += s_att[i] * __bfloat162float(Hbf[(long)s_col[i] * DH + tid]);
        } else {
            for (int i = 0; i < c; i++)
                acc += s_att[i] * HCoff[(long)s_col[i] * 512 + tid];
        }
    }
    if (fast) acc = g_wval * ((float)cs[tid] - acc);
    Hout[(long)r * DH + tid] = acc;
}

// ---------------- SE + consistency ----------------------------------------------
__global__ void se_kernel(const float* __restrict__ H1o, const float* __restrict__ H2o) {
    int t = blockIdx.x * blockDim.x + threadIdx.x;
    int i = t >> 8, d = t & 255;
    float h1 = H1o[t], h2 = H2o[t];
    float hc1, hc2;
    if (g_wflag) {
        float c = g_wval;
        hc1 = c * ((float)g_cs[d]       - h1);
        hc2 = c * ((float)g_cs[256 + d] - h2);
    } else {
        hc1 = g_HC[(long)i * 512 + d];
        hc2 = g_HC[(long)i * 512 + 256 + d];
    }
    float e1 = h1 - hc1, e2 = h2 - hc2, ec = h1 - h2;
    double se   = 0.5 * ((double)e1 * e1 + (double)e2 * e2);
    double cons = (double)ec * ec;
    se   = block_reduce_d(se);
    cons = block_reduce_d(cons);
    if (threadIdx.x == 0) {
        atomicAdd(&g_acc[ACC_SE],   se);
        atomicAdd(&g_acc[ACC_CONS], cons);
    }
}

// ---------------- dense (CE) loss ------------------------------------------------
__global__ void mprep2_kernel(const float* __restrict__ fc1w, const float* __restrict__ fc1b,
                              const float* __restrict__ fczw, const float* __restrict__ fczb,
                              const float* __restrict__ fc2w, const float* __restrict__ fc2b,
                              const float* __restrict__ fcz2w, const float* __restrict__ fcz2b,
                              float* __restrict__ M1o, float* __restrict__ b1o,
                              float* __restrict__ M2o, float* __restrict__ b2o) {
    const float* fw  = blockIdx.x ? fc2w  : fc1w;
    const float* fb  = blockIdx.x ? fc2b  : fc1b;
    const float* fzw = blockIdx.x ? fcz2w : fczw;
    const float* fzb = blockIdx.x ? fcz2b : fczb;
    float* M = blockIdx.x ? M2o : M1o;
    float* bout = blockIdx.x ? b2o : b1o;
    int tid = threadIdx.x;
    for (int o = tid; o < NCLS * DH; o += blockDim.x) {
        int c = o / DH, d = o % DH;
        float s = 0.f;
        for (int k = 0; k < 512; k++) s += fzw[c * 512 + k] * fw[k * DH + d];
        M[o] = s;
    }
    if (tid < NCLS) {
        float s = 0.f;
        for (int k = 0; k < 512; k++) s += fzw[tid * 512 + k] * fb[k];
        bout[tid] = s + fzb[tid];
    }
}

__global__ void dense2_kernel(const float* __restrict__ He1, const float* __restrict__ M1,
                              const float* __restrict__ b1,
                              const float* __restrict__ He2, const float* __restrict__ M2,
                              const float* __restrict__ b2, const int* __restrict__ p) {
    int gw   = (blockIdx.x * blockDim.x + threadIdx.x) >> 5;
    int lane = threadIdx.x & 31;
    double part = 0.0;
    if (gw < 2 * NN) {
        int view2 = gw >= NN;
        int row = view2 ? gw - NN : gw;
        const float* h = (view2 ? He2 : He1) + (long)row * DH;
        const float* M = view2 ? M2 : M1;
        const float* bv = view2 ? b2 : b1;
        float l[NCLS] = {0.f, 0.f, 0.f, 0.f, 0.f, 0.f};
        for (int d = lane; d < DH; d += 32) {
            float hv = h[d];
#pragma unroll
            for (int c = 0; c < NCLS; c++) l[c] += hv * M[c * DH + d];
        }
#pragma unroll
        for (int c = 0; c < NCLS; c++)
#pragma unroll
            for (int o = 16; o; o >>= 1) l[c] += __shfl_xor_sync(0xffffffffu, l[c], o);
        if (lane == 0) {
            float mx = -1e30f;
#pragma unroll
            for (int c = 0; c < NCLS; c++) { l[c] += bv[c]; mx = fmaxf(mx, l[c]); }
            float se = 0.f;
#pragma unroll
            for (int c = 0; c < NCLS; c++) se += expf(l[c] - mx);
            float lse = mx + logf(se);
            part = (double)(lse - l[p[row]]);
        }
    }
    double tot = block_reduce_d(part);
    if (threadIdx.x == 0) atomicAdd(&g_acc[ACC_DENSE], tot);
}

__global__ void struct2_kernel(const __nv_bfloat16* __restrict__ Hbf1,
                               const int* __restrict__ S1, const int* __restrict__ R1,
                               const __nv_bfloat16* __restrict__ Hbf2,
                               const int* __restrict__ S2, const int* __restrict__ R2) {
    int warp = (blockIdx.x * blockDim.x + threadIdx.x) >> 5;
    int lane = threadIdx.x & 31;
    const int wpv = NE / 4;
    int view2 = warp >= wpv;
    int w = view2 ? warp - wpv : warp;
    const __nv_bfloat16* Hbf = view2 ? Hbf2 : Hbf1;
    const int* S = view2 ? S2 : S1;
    const int* R = view2 ? R2 : R1;
    double part = 0.0;
#pragma unroll
    for (int t = 0; t < 4; t++) {
        int ge = w * 4 + t;
        if (ge < NE) {
            const __nv_bfloat16* a = Hbf + (long)S[ge] * DH + lane * 8;
            const __nv_bfloat16* b = Hbf + (long)R[ge] * DH + lane * 8;
            uint4 va = *(const uint4*)a;
            uint4 vb = *(const uint4*)b;
            const __nv_bfloat162* pa = (const __nv_bfloat162*)&va;
            const __nv_bfloat162* pb = (const __nv_bfloat162*)&vb;
            float dot = 0.f;
#pragma unroll
            for (int j = 0; j < 4; j++) {
                float2 fa = __bfloat1622float2(pa[j]);
                float2 fb = __bfloat1622float2(pb[j]);
                dot += fa.x * fb.x + fa.y * fb.y;
            }
#pragma unroll
            for (int o = 16; o; o >>= 1) dot += __shfl_xor_sync(0xffffffffu, dot, o);
            if (lane == 0) {
                float x = dot;
                float sp = (x > 0.f) ? log1pf(expf(-x)) : (-x + log1pf(expf(x)));
                part += (double)sp;
            }
        }
    }
    double tot = block_reduce_d(part);
    if (threadIdx.x == 0) atomicAdd(&g_acc[ACC_STRUCT], tot);
}

// ---------------- finalize ---------------------------------------------------------
__global__ void final_kernel(float* __restrict__ out) {
    double feat = g_acc[ACC_FEAT], se = g_acc[ACC_SE], sreg = g_acc[ACC_SREG];
    double dense = g_acc[ACC_DENSE];
    double st = g_acc[ACC_STRUCT], cons = g_acc[ACC_CONS];
    double cq = g_wflag ? fabs((double)g_wval) * g_acc[ACC_CQT] : g_acc[ACC_CQ];
    double pre  = feat + st + 10.0 * se + 0.01 * cons + sreg;
    double loss = 0.01 * feat + st + 10.0 * se + 0.001 * cons + sreg + 5.0 * cq + 5.0 * dense;
    out[0] = (float)pre;  out[1] = (float)loss; out[2] = (float)dense;
    out[3] = (float)feat; out[4] = (float)st;   out[5] = (float)se;
    out[OFF_CONS] = (float)cons; out[OFF_SREG] = (float)sreg; out[OFF_CQ] = (float)cq;
}

// ---------------- launch -------------------------------------------------------------
extern "C" void kernel_launch(void* const* d_in, const int* in_sizes, int n_in,
                              void* d_out, int out_size) {
    const float* X     = (const float*)d_in[0];
    const float* X2    = (const float*)d_in[1];
    const float* Theta = (const float*)d_in[2];
    const int*   Aidx  = (const int*)d_in[3];
    const int*   A2idx = (const int*)d_in[5];
    const int*   S     = (const int*)d_in[7];
    const int*   R     = (const int*)d_in[8];
    const int*   S2    = (const int*)d_in[9];
    const int*   R2    = (const int*)d_in[10];
    const int*   p     = (const int*)d_in[11];
    const float* W0    = (const float*)d_in[13];
    const float* v00   = (const float*)d_in[14];
    const float* v10   = (const float*)d_in[15];
    const float* weight= (const float*)d_in[16];
    const float* fc1w  = (const float*)d_in[17];
    const float* fc1b  = (const float*)d_in[18];
    const float* fczw  = (const float*)d_in[19];
    const float* fczb  = (const float*)d_in[20];
    const float* fc2w  = (const float*)d_in[21];
    const float* fc2b  = (const float*)d_in[22];
    const float* fcz2w = (const float*)d_in[23];
    const float* fcz2b = (const float*)d_in[24];

    float* out   = (float*)d_out;
    float* Henc1 = out + OFF_H1;
    float* Henc2 = out + OFF_H2;
    float* coef  = out + OFF_COEF;
    const int* rowA = Aidx,  *colA = Aidx  + NE;
    const int* rowB = A2idx, *colB = A2idx + NE;

    float *pH1, *pH2, *pHC, *pHCe1, *pHCe2;
    float *pf1a, *pf2a, *pf1b, *pf2b, *patt1, *patt2;
    float *pM1, *pM2, *pb1, *pb2;
    double *pcs;
    __nv_bfloat16 *pHcatT, *pHbf1, *pHbf2;
    int *pcnt1, *pcnt2, *prp1, *prp2, *pcur1, *pcur2, *pecsr1, *pecsr2;
    cudaGetSymbolAddress((void**)&pH1, g_H1);
    cudaGetSymbolAddress((void**)&pH2, g_H2);
    cudaGetSymbolAddress((void**)&pHC, g_HC);
    cudaGetSymbolAddress((void**)&pHCe1, g_HCenc1);
    cudaGetSymbolAddress((void**)&pHCe2, g_HCenc2);
    cudaGetSymbolAddress((void**)&pcs, g_cs);
    cudaGetSymbolAddress((void**)&pHbf1, g_Hbf1);
    cudaGetSymbolAddress((void**)&pHbf2, g_Hbf2);
    cudaGetSymbolAddress((void**)&pf1a, g_f1a);
    cudaGetSymbolAddress((void**)&pf2a, g_f2a);
    cudaGetSymbolAddress((void**)&pf1b, g_f1b);
    cudaGetSymbolAddress((void**)&pf2b, g_f2b);
    cudaGetSymbolAddress((void**)&patt1, g_att1);
    cudaGetSymbolAddress((void**)&patt2, g_att2);
    cudaGetSymbolAddress((void**)&pM1, g_M1);
    cudaGetSymbolAddress((void**)&pM2, g_M2);
    cudaGetSymbolAddress((void**)&pb1, g_b1);
    cudaGetSymbolAddress((void**)&pb2, g_b2);
    cudaGetSymbolAddress((void**)&pHcatT, g_HcatT);
    cudaGetSymbolAddress((void**)&pcnt1, g_cnt1);
    cudaGetSymbolAddress((void**)&pcnt2, g_cnt2);
    cudaGetSymbolAddress((void**)&prp1, g_rp1);
    cudaGetSymbolAddress((void**)&prp2, g_rp2);
    cudaGetSymbolAddress((void**)&pcur1, g_cur1);
    cudaGetSymbolAddress((void**)&pcur2, g_cur2);
    cudaGetSymbolAddress((void**)&pecsr1, g_ecsr1);
    cudaGetSymbolAddress((void**)&pecsr2, g_ecsr2);

    static int init_done = 0;
    static cudaStream_t s1, s2, s3;
    static cudaEvent_t evZ, evW, ev1, evH1, evChk, evCS2, evGM, evS1, evS3, evC1, evC2;
    if (!init_done) {
        cudaFuncSetAttribute(gemm_mma_kernel, cudaFuncAttributeMaxDynamicSharedMemorySize,
                             4 * TILEB);
        cudaFuncSetAttribute(gemm_recx_kernel, cudaFuncAttributeMaxDynamicSharedMemorySize,
                             4 * TILEB);
        cudaFuncSetAttribute(gemm_h_kernel, cudaFuncAttributeMaxDynamicSharedMemorySize,
                             4 * TILEB);
        cudaStreamCreateWithFlags(&s1, cudaStreamNonBlocking);
        cudaStreamCreateWithFlags(&s2, cudaStreamNonBlocking);
        cudaStreamCreateWithFlags(&s3, cudaStreamNonBlocking);
        cudaEventCreateWithFlags(&evZ,   cudaEventDisableTiming);
        cudaEventCreateWithFlags(&evW,   cudaEventDisableTiming);
        cudaEventCreateWithFlags(&ev1,   cudaEventDisableTiming);
        cudaEventCreateWithFlags(&evH1,  cudaEventDisableTiming);
        cudaEventCreateWithFlags(&evChk, cudaEventDisableTiming);
        cudaEventCreateWithFlags(&evCS2, cudaEventDisableTiming);
        cudaEventCreateWithFlags(&evGM,  cudaEventDisableTiming);
        cudaEventCreateWithFlags(&evS1,  cudaEventDisableTiming);
        cudaEventCreateWithFlags(&evS3,  cudaEventDisableTiming);
        cudaEventCreateWithFlags(&evC1,  cudaEventDisableTiming);
        cudaEventCreateWithFlags(&evC2,  cudaEventDisableTiming);
        init_done = 1;
    }

    // ---- fork ----
    zero_kernel<<<32, 256>>>();
    cudaEventRecord(evZ, 0);
    cudaStreamWaitEvent(s1, evZ, 0);
    cudaStreamWaitEvent(s2, evZ, 0);
    cudaStreamWaitEvent(s3, evZ, 0);

    // stream 2 head: CSR-1 build, merged coef pass, Cq fallback
    cnt_kernel<<<NE / 256, 256, 0, s2>>>(rowA, pcnt1);
    scan_kernel<<<1, 1024, 0, s2>>>(pcnt1, prp1, pcur1);
    fill_kernel<<<NE / 256, 256, 0, s2>>>(rowA, pcur1, pecsr1);
    cudaEventRecord(evC1, s2);
    coefall_kernel<<<4096, 256, 0, s2>>>(weight, Theta, coef);
    cudaEventRecord(evChk, s2);
    cqfb_kernel<<<4096, 256, 0, s2>>>(weight, Theta);

    // stream 3 head: CSR-2 build + fc prep
    cnt_kernel<<<NE / 256, 256, 0, s3>>>(rowB, pcnt2);
    scan_kernel<<<1, 1024, 0, s3>>>(pcnt2, prp2, pcur2);
    fill_kernel<<<NE / 256, 256, 0, s3>>>(rowB, pcur2, pecsr2);
    cudaEventRecord(evC2, s3);
    mprep2_kernel<<<2, 256, 0, s3>>>(fc1w, fc1b, fczw, fczb,
                                     fc2w, fc2b, fcz2w, fcz2b, pM1, pb1, pM2, pb2);

    // stream 0: W0 prep + view 1 chain
    w0split_kernel<<<(DH * KHP + 255) / 256, 256>>>(W0);
    w0bf_kernel<<<(DINP * DH + 255) / 256, 256>>>(W0);
    cudaEventRecord(evW, 0);
    gemm_h_kernel<<<dim3(2, NN / 128), 256, 4 * TILEB>>>(X, pH1, v00, v10, pf1a, pf2a);
    cudaStreamWaitEvent(0, evC1, 0);
    att_kernel<<<NN / 8, 256>>>(colA, pf1a, pf2a, prp1, pecsr1, patt1);
    henc_kernel<<<NN, 256>>>(colA, patt1, prp1, pecsr1, pH1, Henc1, pHbf1);
    cudaEventRecord(evH1, 0);
    colsum_kernel<<<NN / 128, 256>>>(Henc1, pcs);

    // stream 1: view 2 chain
    cudaStreamWaitEvent(s1, evW, 0);
    gemm_h_kernel<<<dim3(2, NN / 128), 256, 4 * TILEB, s1>>>(X2, pH2, v00, v10, pf1b, pf2b);
    cudaStreamWaitEvent(s1, evC2, 0);
    att_kernel<<<NN / 8, 256, 0, s1>>>(colB, pf1b, pf2b, prp2, pecsr2, patt2);
    henc_kernel<<<NN, 256, 0, s1>>>(colB, patt2, prp2, pecsr2, pH2, Henc2, pHbf2);
    cudaEventRecord(ev1, s1);
    colsum_kernel<<<NN / 128, 256, 0, s1>>>(Henc2, pcs + 256);
    cudaEventRecord(evCS2, s1);

    // stream 2 tail: fallback tr + gemm (after both Henc)
    cudaStreamWaitEvent(s2, evH1, 0);
    cudaStreamWaitEvent(s2, ev1, 0);
    tr_kernel<<<dim3(NN / 32, 512 / 32), dim3(32, 8), 0, s2>>>(Henc1, Henc2);
    gemm_mma_kernel<<<dim3(512 / 128, NN / 128), 256, 4 * TILEB, s2>>>(coef, pHcatT, pHC);
    cudaEventRecord(evGM, s2);

    // stream 3: merged struct + dense losses
    cudaStreamWaitEvent(s3, evH1, 0);
    cudaStreamWaitEvent(s3, ev1, 0);
    struct2_kernel<<<NE / 16, 256, 0, s3>>>(pHbf1, S, R, pHbf2, S2, R2);
    dense2_kernel<<<2 * NN / 8, 256, 0, s3>>>(Henc1, pM1, pb1, Henc2, pM2, pb2, p);
    cudaEventRecord(evS3, s3);

    // stream 0: HCenc (merged fast/fallback) + fused GEMM+feat (view 1) + SE
    cudaStreamWaitEvent(0, evChk, 0);
    cudaStreamWaitEvent(0, evGM, 0);
    henchc_any_kernel<<<NN, 256>>>(colA, patt1, prp1, pecsr1, pHbf1, pHC, pcs, pHCe1);
    gemm_recx_kernel<<<dim3(5, NN / 128), 256, 4 * TILEB>>>(pHCe1, X);
    cudaStreamWaitEvent(0, ev1, 0);
    cudaStreamWaitEvent(0, evCS2, 0);
    se_kernel<<<NN, 256>>>(Henc1, Henc2);

    // stream 1: HCenc + fused GEMM+feat (view 2)
    cudaStreamWaitEvent(s1, evChk, 0);
    cudaStreamWaitEvent(s1, evGM, 0);
    henchc_any_kernel<<<NN, 256, 0, s1>>>(colB, patt2, prp2, pecsr2, pHbf2, pHC + 256,
                                          pcs + 256, pHCe2);
    gemm_recx_kernel<<<dim3(5, NN / 128), 256, 4 * TILEB, s1>>>(pHCe2, X2);
    cudaEventRecord(evS1, s1);

    // ---- final join ----
    cudaStreamWaitEvent(0, evS1, 0);
    cudaStreamWaitEvent(0, evS3, 0);
    final_kernel<<<1, 1>>>(out);
}